// round 14
// baseline (speedup 1.0000x reference)
#include <cuda_runtime.h>
#include <cuda_fp16.h>
#include <cstdint>
#include <cstring>

#define BB   8
#define CC   256
#define DD_  16
#define HH_  32
#define WW_  32
#define SS   8
#define NN   16384
#define PLANE 1024
#define NTAP 27
#define BROWS 224            // padded mo rows (28 tiles of 8)
#define B_IMG 28672          // bytes per kchunk W' image

// GEMM smem offsets (bytes)
#define XF0_OFF 0            // fp32 x chunk buf0: 64c x 128n x 4B = 32KB
#define XF1_OFF 32768
#define XH_OFF  65536        // fp16 swizzled x tile: 128 rows x 128B
#define B0_OFF  81920
#define B1_OFF  110592
#define GEMM_SMEM 139264

// fused shiftadd+einsum
#define NK 16
#define KW 64
#define XST 72               // halfs per x row (144B, conflict-free ldmatrix)
#define SELROW 1032          // halfs per sel row (2064B; same bank class as 144)
#define E_SX_HALFS  (256 * XST)            // per x buffer (36,864B)
#define E_SEL_BASE  (3 * E_SX_HALFS)       // half-index where sel starts
#define E_SEL_HALFS (16 * SELROW)
#define EINSUM_SMEM ((3 * E_SX_HALFS + E_SEL_HALFS) * 2)   // 143,616 bytes
#define ETHREADS 512

typedef unsigned int u32;
typedef unsigned long long ull;

// ---------------- scratch ----------------
__device__ __half g_u3[(size_t)BB * NTAP * NN * SS];   // [b][tap][m][s]
__device__ u32    g_xh2[(size_t)BB * (CC / 2) * NN];   // [b][cpair][n] fp16 pairs
__device__ float  g_partial[NK * BB * SS * CC];
__device__ int4   g_Bh4[4 * BROWS * 8];                // 4 kchunks x 224 rows x 128B
__device__ u32    g_ctr;                               // last-CTA counter (reset each run)

// ---------------- helpers ----------------
__device__ __forceinline__ u32 smem_u32(const void* p) {
    u32 a;
    asm("{ .reg .u64 t; cvta.to.shared.u64 t, %1; cvt.u32.u64 %0, t; }"
        : "=r"(a) : "l"(p));
    return a;
}
__device__ __forceinline__ void ldm4(u32* r, u32 addr) {
    asm volatile("ldmatrix.sync.aligned.m8n8.x4.shared.b16 {%0,%1,%2,%3}, [%4];"
                 : "=r"(r[0]), "=r"(r[1]), "=r"(r[2]), "=r"(r[3]) : "r"(addr));
}
__device__ __forceinline__ void mma16816(float* c, const u32* a, const u32* b) {
    asm volatile("mma.sync.aligned.m16n8k16.row.col.f32.f16.f16.f32 "
                 "{%0,%1,%2,%3}, {%4,%5,%6,%7}, {%8,%9}, {%0,%1,%2,%3};"
                 : "+f"(c[0]), "+f"(c[1]), "+f"(c[2]), "+f"(c[3])
                 : "r"(a[0]), "r"(a[1]), "r"(a[2]), "r"(a[3]),
                   "r"(b[0]), "r"(b[1]));
}
__device__ __forceinline__ void cp_async16(u32 dst, const void* src) {
    asm volatile("cp.async.cg.shared.global [%0], [%1], 16;"
                 :: "r"(dst), "l"(src) : "memory");
}
#define CP_COMMIT() asm volatile("cp.async.commit_group;" ::: "memory")
#define CP_WAIT0()  asm volatile("cp.async.wait_group 0;" ::: "memory")

__device__ __forceinline__ float fast_sigmoid(float v) {
    return 1.0f / (1.0f + __expf(-v));
}

// ============================================================================
// K0: prep W' -> fp16 SW128-swizzled smem image per kchunk.
// ============================================================================
__global__ void __launch_bounds__(256) prep_kernel(const float* __restrict__ Wc) {
    const int mo = blockIdx.x;
    const int c  = threadIdx.x;
    float w = 0.0f;
    if (mo < 216) {
        int s = mo & 7, tap = mo >> 3;
        w = Wc[((size_t)s * CC + c) * 27 + tap];
    }
    __half h = __float2half_rn(w);
    const int kc = c >> 6;
    const u32 kb = (u32)((c & 63) * 2) ^ (u32)((mo & 7) << 4);
    const size_t idx = (size_t)kc * (BROWS * 64) + ((u32)mo * 128 + kb) / 2;
    unsigned short hb;
    memcpy(&hb, &h, 2);
    ((unsigned short*)g_Bh4)[idx] = hb;
}

// ============================================================================
// K1: GEMM u[m][mo] = sum_k x[k][m] * W'[mo][k], cp.async double-buffered.
// grid = B*128, block 256 (8 warps = 4 m-groups x 2 n-halves).  [R12 best]
// ============================================================================
__global__ void __launch_bounds__(256) gemm_kernel(const float* __restrict__ x) {
    extern __shared__ char smem[];
    const u32 sb = smem_u32(smem);
    const int tid = threadIdx.x, lane = tid & 31, warp = tid >> 5;
    const int mg = warp & 3, nh = warp >> 2;
    const int b  = blockIdx.x >> 7;
    const int n0 = (blockIdx.x & 127) * 128;

    float acc[7][2][2][4];
#pragma unroll
    for (int p = 0; p < 7; p++)
#pragma unroll
        for (int t = 0; t < 2; t++)
#pragma unroll
            for (int m = 0; m < 2; m++)
#pragma unroll
                for (int i = 0; i < 4; i++) acc[p][t][m][i] = 0.0f;

    const u32 xm     = (u32)(lane & 7) << 4;
    const int arow   = (lane & 7) + ((lane >> 3) & 1) * 8;
    const u32 a_ksel = (u32)((lane >> 4) & 1) * 16;
    const u32 b_ksel = (u32)((lane >> 3) & 1) * 16;
    const int btile  = (lane >> 4);
    const int brow   = lane & 7;

    const int mt0 = mg * 32;
    const u32 aXh0 = sb + XH_OFF + (u32)(mt0 + arow) * 128;
    const u32 aXh1 = aXh0 + 16 * 128;

    const float* xg = x + (size_t)b * CC * NN + n0;
    const int cm  = tid & 127;
    const int ckh = tid >> 7;
    const u32 cxm = (u32)(cm & 7) << 4;
    u32* xh_out = g_xh2 + (size_t)b * (CC / 2) * NN + n0 + cm;

    auto fill_x = [&](int kc) {
        const u32 dst = sb + (u32)((kc & 1) ? XF1_OFF : XF0_OFF);
#pragma unroll
        for (int p = 0; p < 8; p++) {
            int u = tid + p * 256;
            int row = u >> 5, col = u & 31;
            cp_async16(dst + (u32)row * 512 + (u32)col * 16,
                       xg + (size_t)(kc * 64 + row) * NN + col * 4);
        }
    };
    auto fill_B = [&](int kc) {
        const u32 dst = sb + (u32)((kc & 1) ? B1_OFF : B0_OFF);
        const char* src = ((const char*)g_Bh4) + (size_t)kc * B_IMG;
#pragma unroll
        for (int p = 0; p < 7; p++) {
            int u = tid + p * 256;
            cp_async16(dst + (u32)u * 16, src + (size_t)u * 16);
        }
    };

    fill_x(0); fill_B(0); CP_COMMIT();

#pragma unroll 1
    for (int kc = 0; kc < 4; kc++) {
        CP_WAIT0();
        __syncthreads();
        if (kc < 3) { fill_x(kc + 1); fill_B(kc + 1); CP_COMMIT(); }

        // ---- convert fp32 smem -> fp16 swizzled tile + g_xh2 dump ----
        {
            const float* xf = (const float*)(smem + ((kc & 1) ? XF1_OFF : XF0_OFF));
            u32 hp[16];
#pragma unroll
            for (int u = 0; u < 16; u++) {
                float f0 = xf[(ckh * 32 + 2 * u) * 128 + cm];
                float f1 = xf[(ckh * 32 + 2 * u + 1) * 128 + cm];
                __half2 h2 = __floats2half2_rn(f0, f1);
                memcpy(&hp[u], &h2, 4);
            }
#pragma unroll
            for (int j = 0; j < 4; j++) {
                u32 off = ((u32)(ckh * 64 + j * 16)) ^ cxm;
                uint4 v4 = make_uint4(hp[4 * j], hp[4 * j + 1],
                                      hp[4 * j + 2], hp[4 * j + 3]);
                *(uint4*)(smem + XH_OFF + cm * 128 + off) = v4;
            }
            u32* xo = xh_out + (size_t)(kc * 32 + ckh * 16) * NN;
#pragma unroll
            for (int u = 0; u < 16; u++)
                xo[(size_t)u * NN] = hp[u];
        }
        __syncthreads();

        // ---- compute: 4 k16 steps ----
        const u32 Bbase = sb + (u32)((kc & 1) ? B1_OFF : B0_OFF);
#pragma unroll
        for (int j = 0; j < 4; j++) {
            const u32 ka  = ((u32)(j * 32) + a_ksel) ^ xm;
            const u32 kb2 = ((u32)(j * 32) + b_ksel) ^ xm;
            u32 Ah0[4], Ah1[4];
            ldm4(Ah0, aXh0 + ka); ldm4(Ah1, aXh1 + ka);
#pragma unroll
            for (int p = 0; p < 7; p++) {
                const int tile = nh * 14 + 2 * p + btile;
                const u32 boff = (u32)(tile * 8 + brow) * 128 + kb2;
                u32 Bf[4];
                ldm4(Bf, Bbase + boff);
                mma16816(acc[p][0][0], Ah0, Bf);
                mma16816(acc[p][0][1], Ah1, Bf);
                mma16816(acc[p][1][0], Ah0, Bf + 2);
                mma16816(acc[p][1][1], Ah1, Bf + 2);
            }
        }
    }

    // ---- epilogue: fp16 u stores (tile == tap) ----
    const int mrow = lane >> 2;
    const int q    = lane & 3;
    u32* up = (u32*)g_u3;
#pragma unroll
    for (int p = 0; p < 7; p++)
#pragma unroll
        for (int tt = 0; tt < 2; tt++) {
            const int tile = nh * 14 + 2 * p + tt;
            if (tile >= NTAP) continue;
#pragma unroll
            for (int mi = 0; mi < 2; mi++) {
                const float* cf = acc[p][tt][mi];
                const int m = n0 + mt0 + mi * 16 + mrow;
                const size_t base = ((size_t)(b * NTAP + tile) * NN + m) * 4 + q;
                __half2 h01 = __floats2half2_rn(cf[0], cf[1]);
                __half2 h23 = __floats2half2_rn(cf[2], cf[3]);
                u32 w01, w23;
                memcpy(&w01, &h01, 4); memcpy(&w23, &h23, 4);
                up[base]      = w01;
                up[base + 32] = w23;
            }
        }
}

// ============================================================================
// K2: FUSED shift-add + sigmoid + einsum + final reduction (last CTA).
// grid = B*NK = 128 CTAs, 512 threads.
// ============================================================================
__global__ void __launch_bounds__(ETHREADS) einsum_fused_kernel(
    const float* __restrict__ bias, float* __restrict__ out)
{
    extern __shared__ __half esm[];
    __half* sx0  = esm;                    // 3 x E_SX_HALFS
    __half* ssel = esm + E_SEL_BASE;       // 16 x SELROW

    const int b = blockIdx.x >> 4;
    const int v = blockIdx.x & (NK - 1);
    const int tid = threadIdx.x, lane = tid & 31, warp = tid >> 5;
    const int kbase = v * (NN / NK);       // 1024 n per split

    // zero sel rows 8..15
    for (int i = tid; i < 8 * SELROW; i += ETHREADS)
        ssel[8 * SELROW + i] = __float2half(0.0f);

    // ---- Phase 1: shift-add + sigmoid for n in [kbase, kbase+1024) ----
    {
        const uint4* ub = (const uint4*)g_u3 + (size_t)b * NTAP * NN;
        float bs[SS];
#pragma unroll
        for (int s = 0; s < SS; s++) bs[s] = bias[s];

#pragma unroll
        for (int pass = 0; pass < 2; pass++) {
            const int nl = pass * ETHREADS + tid;
            const int n  = kbase + nl;
            const int d = n >> 10, h = (n >> 5) & 31, w = n & 31;

            float acc[SS];
#pragma unroll
            for (int s = 0; s < SS; s++) acc[s] = bs[s];

#pragma unroll
            for (int kd = 0; kd < 3; kd++) {
                const int dd = d + kd - 1;
                if ((unsigned)dd >= (unsigned)DD_) continue;
#pragma unroll
                for (int kh = 0; kh < 3; kh++) {
                    const int hh = h + kh - 1;
                    if ((unsigned)hh >= (unsigned)HH_) continue;
#pragma unroll
                    for (int kw = 0; kw < 3; kw++) {
                        const int ww = w + kw - 1;
                        if ((unsigned)ww >= (unsigned)WW_) continue;
                        const int tap = (kd * 3 + kh) * 3 + kw;
                        const int m = dd * PLANE + hh * WW_ + ww;
                        uint4 vv = ub[(size_t)tap * NN + m];
                        __half2 p0, p1, p2, p3;
                        memcpy(&p0, &vv.x, 4); memcpy(&p1, &vv.y, 4);
                        memcpy(&p2, &vv.z, 4); memcpy(&p3, &vv.w, 4);
                        float2 f0 = __half22float2(p0), f1 = __half22float2(p1);
                        float2 f2 = __half22float2(p2), f3 = __half22float2(p3);
                        acc[0] += f0.x; acc[1] += f0.y; acc[2] += f1.x; acc[3] += f1.y;
                        acc[4] += f2.x; acc[5] += f2.y; acc[6] += f3.x; acc[7] += f3.y;
                    }
                }
            }
#pragma unroll
            for (int s = 0; s < SS; s++)
                ssel[s * SELROW + nl] = __float2half_rn(fast_sigmoid(acc[s]));
        }
    }

    // ---- Phase 2: einsum over 16 windows of 64 n ----
    const u32* xsrc = g_xh2 + (size_t)b * (CC / 2) * NN + kbase;

    float acc0[4], acc1[4];
#pragma unroll
    for (int i = 0; i < 4; i++) { acc0[i] = 0.0f; acc1[i] = 0.0f; }

    const u32 sxb  = smem_u32(sx0);
    const u32 selb = smem_u32(ssel);
    const int a_row  = (lane & 7) + ((lane >> 3) & 1) * 8;
    const u32 a_kblk = (u32)((lane >> 4) & 1) * 8;      // halfs
    const int bt_loc = (lane >> 4);                     // B-addressing role only
    const u32 b_kblk = (u32)((lane >> 3) & 1) * 8;      // halfs
    const int b_row  = lane & 7;
    const int ct     = warp * 2 + bt_loc;
    const u32 bAddrC = (u32)(ct * 8 + b_row) * (XST * 2) + b_kblk * 2;
    const u32 aAddrC = selb + (u32)a_row * (SELROW * 2) + a_kblk * 2;

    const int row_ = tid >> 4, q_ = tid & 15;   // LOADX/STOREX lane mapping

#define LOADX(xr, w) do {                                                     \
    _Pragma("unroll")                                                         \
    for (int p = 0; p < 4; p++) {                                             \
        int r2 = row_ + p * 32;                                               \
        (xr)[p] = *(const uint4*)(xsrc + (size_t)r2 * NN + (w) * KW + q_ * 4);\
    }                                                                         \
} while (0)

#define STOREX(bufi, xr) do {                                                 \
    __half* sxw = sx0 + (bufi) * E_SX_HALFS;                                  \
    _Pragma("unroll")                                                         \
    for (int p = 0; p < 4; p++) {                                             \
        int r2 = row_ + p * 32;                                               \
        u32 e01 = __byte_perm((xr)[p].x, (xr)[p].y, 0x5410);                  \
        u32 e23 = __byte_perm((xr)[p].z, (xr)[p].w, 0x5410);                  \
        u32 o01 = __byte_perm((xr)[p].x, (xr)[p].y, 0x7632);                  \
        u32 o23 = __byte_perm((xr)[p].z, (xr)[p].w, 0x7632);                  \
        *(uint2*)&sxw[(2 * r2) * XST + q_ * 4]     = make_uint2(e01, e23);    \
        *(uint2*)&sxw[(2 * r2 + 1) * XST + q_ * 4] = make_uint2(o01, o23);    \
    }                                                                         \
} while (0)

#define COMPUTEX(bufi, w) do {                                                \
    const u32 sxbase = sxb + (u32)(bufi) * E_SX_HALFS * 2;                    \
    _Pragma("unroll")                                                         \
    for (int ks = 0; ks < KW / 16; ks++) {                                    \
        u32 A[4];                                                             \
        ldm4(A, aAddrC + ((u32)((w) * KW + ks * 16)) * 2);                    \
        u32 Bf[4];                                                            \
        ldm4(Bf, sxbase + bAddrC + (u32)(ks * 16) * 2);                       \
        mma16816(acc0, A, Bf);                                                \
        mma16816(acc1, A, Bf + 2);                                            \
    }                                                                         \
} while (0)

    uint4 xrA[4], xrB[4];
    LOADX(xrA, 0);
    LOADX(xrB, 1);

#pragma unroll 1
    for (int wp = 0; wp < 8; wp++) {
        const int w0 = 2 * wp, w1 = w0 + 1;
        STOREX(w0 % 3, xrA);
        __syncthreads();
        if (w0 + 2 < 16) LOADX(xrA, w0 + 2);
        COMPUTEX(w0 % 3, w0);
        __syncthreads();
        STOREX(w1 % 3, xrB);
        __syncthreads();
        if (w1 + 2 < 16) LOADX(xrB, w1 + 2);
        COMPUTEX(w1 % 3, w1);
        __syncthreads();
    }

    // epilogue: acc0 = tile warp*2, acc1 = tile warp*2+1 for ALL lanes.
    const int s = lane >> 2;
    {
        const int c0 = warp * 16 + (lane & 3) * 2;
        float* dst = &g_partial[(((size_t)v * BB + b) * SS + s) * CC + c0];
        dst[0] = acc0[0];
        dst[1] = acc0[1];
        dst[8] = acc1[0];
        dst[9] = acc1[1];
    }

    // ---- last-CTA reduction: out[i] = sum_v partial[v][i] / N ----
    __threadfence();
    __shared__ u32 s_last;
    if (tid == 0) {
        u32 t = atomicAdd(&g_ctr, 1u);
        s_last = (t == (u32)(BB * NK - 1)) ? 1u : 0u;
    }
    __syncthreads();
    if (s_last) {
        for (int i = tid; i < BB * SS * CC; i += ETHREADS) {
            float sum = 0.f;
#pragma unroll
            for (int vv = 0; vv < NK; vv++)
                sum += g_partial[(size_t)vv * (BB * SS * CC) + i];
            out[i] = sum * (1.0f / (float)NN);
        }
        if (tid == 0) g_ctr = 0;           // reset for next graph replay
    }
#undef LOADX
#undef STOREX
#undef COMPUTEX
}

// ============================================================================
extern "C" void kernel_launch(void* const* d_in, const int* in_sizes, int n_in,
                              void* d_out, int out_size) {
    const float* x    = (const float*)d_in[0];   // [8,256,16,32,32]
    const float* Wc   = (const float*)d_in[1];   // [8,256,3,3,3]
    const float* bias = (const float*)d_in[2];   // [8]
    float* out = (float*)d_out;                  // [8,8,256]

    cudaFuncSetAttribute(gemm_kernel,
                         cudaFuncAttributeMaxDynamicSharedMemorySize, GEMM_SMEM);
    cudaFuncSetAttribute(einsum_fused_kernel,
                         cudaFuncAttributeMaxDynamicSharedMemorySize, EINSUM_SMEM);

    prep_kernel<<<BROWS, 256>>>(Wc);
    gemm_kernel<<<BB * (NN / 128), 256, GEMM_SMEM>>>(x);
    einsum_fused_kernel<<<BB * NK, ETHREADS, EINSUM_SMEM>>>(bias, out);
}

// round 15
// speedup vs baseline: 1.1147x; 1.1147x over previous
#include <cuda_runtime.h>
#include <cuda_fp16.h>
#include <cstdint>
#include <cstring>

#define BB   8
#define CC   256
#define DD_  16
#define HH_  32
#define WW_  32
#define SS   8
#define NN   16384
#define PLANE 1024
#define NTAP 27
#define BROWS 224            // padded mo rows (28 tiles of 8)
#define B_IMG 28672          // bytes per kchunk W' image

// GEMM smem offsets (bytes) — single fp32 x buffer, 104KB total -> 2 CTAs/SM
#define XF_OFF  0            // fp32 x chunk: 64c x 128n x 4B = 32KB
#define XH_OFF  32768        // fp16 swizzled x tile: 128 rows x 128B = 16KB
#define B0_OFF  49152
#define B1_OFF  77824
#define GEMM_SMEM 106496

// fused shiftadd+einsum
#define NK 16
#define KW 64
#define XST 72               // halfs per x row (144B, conflict-free ldmatrix)
#define SELROW 1032          // halfs per sel row (2064B; same bank class as 144)
#define E_SX_HALFS  (256 * XST)            // per x buffer (36,864B)
#define E_SEL_BASE  (3 * E_SX_HALFS)       // half-index where sel starts
#define E_SEL_HALFS (16 * SELROW)
#define EINSUM_SMEM ((3 * E_SX_HALFS + E_SEL_HALFS) * 2)   // 143,616 bytes
#define ETHREADS 512

typedef unsigned int u32;
typedef unsigned long long ull;

// ---------------- scratch ----------------
__device__ __half g_u3[(size_t)BB * NTAP * NN * SS];   // [b][tap][m][s]
__device__ u32    g_xh2[(size_t)BB * (CC / 2) * NN];   // [b][cpair][n] fp16 pairs
__device__ float  g_partial[NK * BB * SS * CC];
__device__ int4   g_Bh4[4 * BROWS * 8];                // 4 kchunks x 224 rows x 128B

// ---------------- helpers ----------------
__device__ __forceinline__ u32 smem_u32(const void* p) {
    u32 a;
    asm("{ .reg .u64 t; cvta.to.shared.u64 t, %1; cvt.u32.u64 %0, t; }"
        : "=r"(a) : "l"(p));
    return a;
}
__device__ __forceinline__ void ldm4(u32* r, u32 addr) {
    asm volatile("ldmatrix.sync.aligned.m8n8.x4.shared.b16 {%0,%1,%2,%3}, [%4];"
                 : "=r"(r[0]), "=r"(r[1]), "=r"(r[2]), "=r"(r[3]) : "r"(addr));
}
__device__ __forceinline__ void mma16816(float* c, const u32* a, const u32* b) {
    asm volatile("mma.sync.aligned.m16n8k16.row.col.f32.f16.f16.f32 "
                 "{%0,%1,%2,%3}, {%4,%5,%6,%7}, {%8,%9}, {%0,%1,%2,%3};"
                 : "+f"(c[0]), "+f"(c[1]), "+f"(c[2]), "+f"(c[3])
                 : "r"(a[0]), "r"(a[1]), "r"(a[2]), "r"(a[3]),
                   "r"(b[0]), "r"(b[1]));
}
__device__ __forceinline__ void cp_async16(u32 dst, const void* src) {
    asm volatile("cp.async.cg.shared.global [%0], [%1], 16;"
                 :: "r"(dst), "l"(src) : "memory");
}
#define CP_COMMIT() asm volatile("cp.async.commit_group;" ::: "memory")
#define CP_WAIT0()  asm volatile("cp.async.wait_group 0;" ::: "memory")

__device__ __forceinline__ float fast_sigmoid(float v) {
    return 1.0f / (1.0f + __expf(-v));
}

// ============================================================================
// K0: prep W' -> fp16 SW128-swizzled smem image per kchunk.
// ============================================================================
__global__ void __launch_bounds__(256) prep_kernel(const float* __restrict__ Wc) {
    const int mo = blockIdx.x;
    const int c  = threadIdx.x;
    float w = 0.0f;
    if (mo < 216) {
        int s = mo & 7, tap = mo >> 3;
        w = Wc[((size_t)s * CC + c) * 27 + tap];
    }
    __half h = __float2half_rn(w);
    const int kc = c >> 6;
    const u32 kb = (u32)((c & 63) * 2) ^ (u32)((mo & 7) << 4);
    const size_t idx = (size_t)kc * (BROWS * 64) + ((u32)mo * 128 + kb) / 2;
    unsigned short hb;
    memcpy(&hb, &h, 2);
    ((unsigned short*)g_Bh4)[idx] = hb;
}

// ============================================================================
// K1: GEMM u[m][mo] = sum_k x[k][m] * W'[mo][k].
// grid = B*128, block 256 (8 warps = 4 m-groups x 2 n-halves).
// Single x-staging buffer (104KB smem total -> 2 CTAs/SM); B double-buffered.
// Per kc: wait -> convert -> sync -> prefetch(kc+1) -> compute(kc).
// ============================================================================
__global__ void __launch_bounds__(256) gemm_kernel(const float* __restrict__ x) {
    extern __shared__ char smem[];
    const u32 sb = smem_u32(smem);
    const int tid = threadIdx.x, lane = tid & 31, warp = tid >> 5;
    const int mg = warp & 3, nh = warp >> 2;
    const int b  = blockIdx.x >> 7;
    const int n0 = (blockIdx.x & 127) * 128;

    float acc[7][2][2][4];
#pragma unroll
    for (int p = 0; p < 7; p++)
#pragma unroll
        for (int t = 0; t < 2; t++)
#pragma unroll
            for (int m = 0; m < 2; m++)
#pragma unroll
                for (int i = 0; i < 4; i++) acc[p][t][m][i] = 0.0f;

    const u32 xm     = (u32)(lane & 7) << 4;
    const int arow   = (lane & 7) + ((lane >> 3) & 1) * 8;
    const u32 a_ksel = (u32)((lane >> 4) & 1) * 16;
    const u32 b_ksel = (u32)((lane >> 3) & 1) * 16;
    const int btile  = (lane >> 4);
    const int brow   = lane & 7;

    const int mt0 = mg * 32;
    const u32 aXh0 = sb + XH_OFF + (u32)(mt0 + arow) * 128;
    const u32 aXh1 = aXh0 + 16 * 128;

    const float* xg = x + (size_t)b * CC * NN + n0;
    const int cm  = tid & 127;
    const int ckh = tid >> 7;
    const u32 cxm = (u32)(cm & 7) << 4;
    u32* xh_out = g_xh2 + (size_t)b * (CC / 2) * NN + n0 + cm;

    auto fill_x = [&](int kc) {
        const u32 dst = sb + XF_OFF;
#pragma unroll
        for (int p = 0; p < 8; p++) {
            int u = tid + p * 256;
            int row = u >> 5, col = u & 31;
            cp_async16(dst + (u32)row * 512 + (u32)col * 16,
                       xg + (size_t)(kc * 64 + row) * NN + col * 4);
        }
    };
    auto fill_B = [&](int kc) {
        const u32 dst = sb + (u32)((kc & 1) ? B1_OFF : B0_OFF);
        const char* src = ((const char*)g_Bh4) + (size_t)kc * B_IMG;
#pragma unroll
        for (int p = 0; p < 7; p++) {
            int u = tid + p * 256;
            cp_async16(dst + (u32)u * 16, src + (size_t)u * 16);
        }
    };

    fill_x(0); fill_B(0); CP_COMMIT();

#pragma unroll 1
    for (int kc = 0; kc < 4; kc++) {
        CP_WAIT0();
        __syncthreads();

        // ---- convert fp32 smem -> fp16 swizzled tile + g_xh2 dump ----
        {
            const float* xf = (const float*)(smem + XF_OFF);
            u32 hp[16];
#pragma unroll
            for (int u = 0; u < 16; u++) {
                float f0 = xf[(ckh * 32 + 2 * u) * 128 + cm];
                float f1 = xf[(ckh * 32 + 2 * u + 1) * 128 + cm];
                __half2 h2 = __floats2half2_rn(f0, f1);
                memcpy(&hp[u], &h2, 4);
            }
#pragma unroll
            for (int j = 0; j < 4; j++) {
                u32 off = ((u32)(ckh * 64 + j * 16)) ^ cxm;
                uint4 v4 = make_uint4(hp[4 * j], hp[4 * j + 1],
                                      hp[4 * j + 2], hp[4 * j + 3]);
                *(uint4*)(smem + XH_OFF + cm * 128 + off) = v4;
            }
            u32* xo = xh_out + (size_t)(kc * 32 + ckh * 16) * NN;
#pragma unroll
            for (int u = 0; u < 16; u++)
                xo[(size_t)u * NN] = hp[u];
        }
        __syncthreads();   // XF consumed by all; XH ready for all

        // ---- prefetch next chunk (x into freed XF, B into other buffer) ----
        if (kc < 3) { fill_x(kc + 1); fill_B(kc + 1); CP_COMMIT(); }

        // ---- compute: 4 k16 steps ----
        const u32 Bbase = sb + (u32)((kc & 1) ? B1_OFF : B0_OFF);
#pragma unroll
        for (int j = 0; j < 4; j++) {
            const u32 ka  = ((u32)(j * 32) + a_ksel) ^ xm;
            const u32 kb2 = ((u32)(j * 32) + b_ksel) ^ xm;
            u32 Ah0[4], Ah1[4];
            ldm4(Ah0, aXh0 + ka); ldm4(Ah1, aXh1 + ka);
#pragma unroll
            for (int p = 0; p < 7; p++) {
                const int tile = nh * 14 + 2 * p + btile;
                const u32 boff = (u32)(tile * 8 + brow) * 128 + kb2;
                u32 Bf[4];
                ldm4(Bf, Bbase + boff);
                mma16816(acc[p][0][0], Ah0, Bf);
                mma16816(acc[p][0][1], Ah1, Bf);
                mma16816(acc[p][1][0], Ah0, Bf + 2);
                mma16816(acc[p][1][1], Ah1, Bf + 2);
            }
        }
    }

    // ---- epilogue: fp16 u stores (tile == tap) ----
    const int mrow = lane >> 2;
    const int q    = lane & 3;
    u32* up = (u32*)g_u3;
#pragma unroll
    for (int p = 0; p < 7; p++)
#pragma unroll
        for (int tt = 0; tt < 2; tt++) {
            const int tile = nh * 14 + 2 * p + tt;
            if (tile >= NTAP) continue;
#pragma unroll
            for (int mi = 0; mi < 2; mi++) {
                const float* cf = acc[p][tt][mi];
                const int m = n0 + mt0 + mi * 16 + mrow;
                const size_t base = ((size_t)(b * NTAP + tile) * NN + m) * 4 + q;
                __half2 h01 = __floats2half2_rn(cf[0], cf[1]);
                __half2 h23 = __floats2half2_rn(cf[2], cf[3]);
                u32 w01, w23;
                memcpy(&w01, &h01, 4); memcpy(&w23, &h23, 4);
                up[base]      = w01;
                up[base + 32] = w23;
            }
        }
}

// ============================================================================
// K2: FUSED shift-add + sigmoid + einsum (tensor cores).   [R12 best]
// grid = B*NK = 128 CTAs, 512 threads.
// ============================================================================
__global__ void __launch_bounds__(ETHREADS) einsum_fused_kernel(
    const float* __restrict__ bias)
{
    extern __shared__ __half esm[];
    __half* sx0  = esm;                    // 3 x E_SX_HALFS
    __half* ssel = esm + E_SEL_BASE;       // 16 x SELROW

    const int b = blockIdx.x >> 4;
    const int v = blockIdx.x & (NK - 1);
    const int tid = threadIdx.x, lane = tid & 31, warp = tid >> 5;
    const int kbase = v * (NN / NK);       // 1024 n per split

    // zero sel rows 8..15
    for (int i = tid; i < 8 * SELROW; i += ETHREADS)
        ssel[8 * SELROW + i] = __float2half(0.0f);

    // ---- Phase 1: shift-add + sigmoid for n in [kbase, kbase+1024) ----
    {
        const uint4* ub = (const uint4*)g_u3 + (size_t)b * NTAP * NN;
        float bs[SS];
#pragma unroll
        for (int s = 0; s < SS; s++) bs[s] = bias[s];

#pragma unroll
        for (int pass = 0; pass < 2; pass++) {
            const int nl = pass * ETHREADS + tid;
            const int n  = kbase + nl;
            const int d = n >> 10, h = (n >> 5) & 31, w = n & 31;

            float acc[SS];
#pragma unroll
            for (int s = 0; s < SS; s++) acc[s] = bs[s];

#pragma unroll
            for (int kd = 0; kd < 3; kd++) {
                const int dd = d + kd - 1;
                if ((unsigned)dd >= (unsigned)DD_) continue;
#pragma unroll
                for (int kh = 0; kh < 3; kh++) {
                    const int hh = h + kh - 1;
                    if ((unsigned)hh >= (unsigned)HH_) continue;
#pragma unroll
                    for (int kw = 0; kw < 3; kw++) {
                        const int ww = w + kw - 1;
                        if ((unsigned)ww >= (unsigned)WW_) continue;
                        const int tap = (kd * 3 + kh) * 3 + kw;
                        const int m = dd * PLANE + hh * WW_ + ww;
                        uint4 vv = ub[(size_t)tap * NN + m];
                        __half2 p0, p1, p2, p3;
                        memcpy(&p0, &vv.x, 4); memcpy(&p1, &vv.y, 4);
                        memcpy(&p2, &vv.z, 4); memcpy(&p3, &vv.w, 4);
                        float2 f0 = __half22float2(p0), f1 = __half22float2(p1);
                        float2 f2 = __half22float2(p2), f3 = __half22float2(p3);
                        acc[0] += f0.x; acc[1] += f0.y; acc[2] += f1.x; acc[3] += f1.y;
                        acc[4] += f2.x; acc[5] += f2.y; acc[6] += f3.x; acc[7] += f3.y;
                    }
                }
            }
#pragma unroll
            for (int s = 0; s < SS; s++)
                ssel[s * SELROW + nl] = __float2half_rn(fast_sigmoid(acc[s]));
        }
    }

    // ---- Phase 2: einsum over 16 windows of 64 n ----
    const u32* xsrc = g_xh2 + (size_t)b * (CC / 2) * NN + kbase;

    float acc0[4], acc1[4];
#pragma unroll
    for (int i = 0; i < 4; i++) { acc0[i] = 0.0f; acc1[i] = 0.0f; }

    const u32 sxb  = smem_u32(sx0);
    const u32 selb = smem_u32(ssel);
    const int a_row  = (lane & 7) + ((lane >> 3) & 1) * 8;
    const u32 a_kblk = (u32)((lane >> 4) & 1) * 8;      // halfs
    const int bt_loc = (lane >> 4);                     // B-addressing role only
    const u32 b_kblk = (u32)((lane >> 3) & 1) * 8;      // halfs
    const int b_row  = lane & 7;
    const int ct     = warp * 2 + bt_loc;
    const u32 bAddrC = (u32)(ct * 8 + b_row) * (XST * 2) + b_kblk * 2;
    const u32 aAddrC = selb + (u32)a_row * (SELROW * 2) + a_kblk * 2;

    const int row_ = tid >> 4, q_ = tid & 15;   // LOADX/STOREX lane mapping

#define LOADX(xr, w) do {                                                     \
    _Pragma("unroll")                                                         \
    for (int p = 0; p < 4; p++) {                                             \
        int r2 = row_ + p * 32;                                               \
        (xr)[p] = *(const uint4*)(xsrc + (size_t)r2 * NN + (w) * KW + q_ * 4);\
    }                                                                         \
} while (0)

#define STOREX(bufi, xr) do {                                                 \
    __half* sxw = sx0 + (bufi) * E_SX_HALFS;                                  \
    _Pragma("unroll")                                                         \
    for (int p = 0; p < 4; p++) {                                             \
        int r2 = row_ + p * 32;                                               \
        u32 e01 = __byte_perm((xr)[p].x, (xr)[p].y, 0x5410);                  \
        u32 e23 = __byte_perm((xr)[p].z, (xr)[p].w, 0x5410);                  \
        u32 o01 = __byte_perm((xr)[p].x, (xr)[p].y, 0x7632);                  \
        u32 o23 = __byte_perm((xr)[p].z, (xr)[p].w, 0x7632);                  \
        *(uint2*)&sxw[(2 * r2) * XST + q_ * 4]     = make_uint2(e01, e23);    \
        *(uint2*)&sxw[(2 * r2 + 1) * XST + q_ * 4] = make_uint2(o01, o23);    \
    }                                                                         \
} while (0)

#define COMPUTEX(bufi, w) do {                                                \
    const u32 sxbase = sxb + (u32)(bufi) * E_SX_HALFS * 2;                    \
    _Pragma("unroll")                                                         \
    for (int ks = 0; ks < KW / 16; ks++) {                                    \
        u32 A[4];                                                             \
        ldm4(A, aAddrC + ((u32)((w) * KW + ks * 16)) * 2);                    \
        u32 Bf[4];                                                            \
        ldm4(Bf, sxbase + bAddrC + (u32)(ks * 16) * 2);                       \
        mma16816(acc0, A, Bf);                                                \
        mma16816(acc1, A, Bf + 2);                                            \
    }                                                                         \
} while (0)

    uint4 xrA[4], xrB[4];
    LOADX(xrA, 0);
    LOADX(xrB, 1);

#pragma unroll 1
    for (int wp = 0; wp < 8; wp++) {
        const int w0 = 2 * wp, w1 = w0 + 1;
        STOREX(w0 % 3, xrA);
        __syncthreads();
        if (w0 + 2 < 16) LOADX(xrA, w0 + 2);
        COMPUTEX(w0 % 3, w0);
        __syncthreads();
        STOREX(w1 % 3, xrB);
        __syncthreads();
        if (w1 + 2 < 16) LOADX(xrB, w1 + 2);
        COMPUTEX(w1 % 3, w1);
        __syncthreads();
    }

    // epilogue: acc0 = tile warp*2, acc1 = tile warp*2+1 for ALL lanes.
    const int s = lane >> 2;
    {
        const int c0 = warp * 16 + (lane & 3) * 2;
        float* dst = &g_partial[(((size_t)v * BB + b) * SS + s) * CC + c0];
        dst[0] = acc0[0];
        dst[1] = acc0[1];
        dst[8] = acc1[0];
        dst[9] = acc1[1];
    }
#undef LOADX
#undef STOREX
#undef COMPUTEX
}

// ============================================================================
// K3: out[i] = sum_v partial[v][i] / N
// ============================================================================
__global__ void __launch_bounds__(256) reduce_kernel(float* __restrict__ out) {
    int i = blockIdx.x * 256 + threadIdx.x;
    if (i < BB * SS * CC) {
        float s = 0.f;
#pragma unroll
        for (int v = 0; v < NK; v++)
            s += g_partial[(size_t)v * (BB * SS * CC) + i];
        out[i] = s * (1.0f / (float)NN);
    }
}

// ============================================================================
extern "C" void kernel_launch(void* const* d_in, const int* in_sizes, int n_in,
                              void* d_out, int out_size) {
    const float* x    = (const float*)d_in[0];   // [8,256,16,32,32]
    const float* Wc   = (const float*)d_in[1];   // [8,256,3,3,3]
    const float* bias = (const float*)d_in[2];   // [8]
    float* out = (float*)d_out;                  // [8,8,256]

    cudaFuncSetAttribute(gemm_kernel,
                         cudaFuncAttributeMaxDynamicSharedMemorySize, GEMM_SMEM);
    cudaFuncSetAttribute(einsum_fused_kernel,
                         cudaFuncAttributeMaxDynamicSharedMemorySize, EINSUM_SMEM);

    prep_kernel<<<BROWS, 256>>>(Wc);
    gemm_kernel<<<BB * (NN / 128), 256, GEMM_SMEM>>>(x);
    einsum_fused_kernel<<<BB * NK, ETHREADS, EINSUM_SMEM>>>(bias);
    reduce_kernel<<<(BB * SS * CC + 255) / 256, 256>>>(out);
}

// round 16
// speedup vs baseline: 1.1512x; 1.0328x over previous
#include <cuda_runtime.h>
#include <cuda_fp16.h>
#include <cstdint>
#include <cstring>

#define BB   8
#define CC   256
#define DD_  16
#define HH_  32
#define WW_  32
#define SS   8
#define NN   16384
#define PLANE 1024
#define NTAP 27
#define BROWS 224            // padded mo rows (28 tiles of 8)
#define B_IMG 28672          // bytes per kchunk W' image

// GEMM smem offsets (bytes) — single fp32 x buffer, 104KB total
#define XF_OFF  0            // fp32 x chunk: 64c x 128n x 4B = 32KB
#define XH_OFF  32768        // fp16 swizzled x tile: 128 rows x 128B = 16KB
#define B0_OFF  49152
#define B1_OFF  77824
#define GEMM_SMEM 106496

// fused shiftadd+einsum
#define NK 16
#define KW 64
#define XST 72               // halfs per x row (144B, conflict-free ldmatrix)
#define SELROW 1032          // halfs per sel row (2064B; same bank class as 144)
#define E_SX_HALFS  (256 * XST)            // per x buffer (36,864B)
#define E_SEL_BASE  (3 * E_SX_HALFS)       // half-index where sel starts
#define E_SEL_HALFS (16 * SELROW)
#define EINSUM_SMEM ((3 * E_SX_HALFS + E_SEL_HALFS) * 2)   // 143,616 bytes
#define ETHREADS 512

typedef unsigned int u32;
typedef unsigned long long ull;

// ---------------- scratch ----------------
__device__ __half g_u3[(size_t)BB * NTAP * NN * SS];   // [b][tap][m][s]
__device__ u32    g_xh2[(size_t)BB * (CC / 2) * NN];   // [b][cpair][n] fp16 pairs
__device__ int4   g_Bh4[4 * BROWS * 8];                // 4 kchunks x 224 rows x 128B

// ---------------- helpers ----------------
__device__ __forceinline__ u32 smem_u32(const void* p) {
    u32 a;
    asm("{ .reg .u64 t; cvta.to.shared.u64 t, %1; cvt.u32.u64 %0, t; }"
        : "=r"(a) : "l"(p));
    return a;
}
__device__ __forceinline__ void ldm4(u32* r, u32 addr) {
    asm volatile("ldmatrix.sync.aligned.m8n8.x4.shared.b16 {%0,%1,%2,%3}, [%4];"
                 : "=r"(r[0]), "=r"(r[1]), "=r"(r[2]), "=r"(r[3]) : "r"(addr));
}
__device__ __forceinline__ void mma16816(float* c, const u32* a, const u32* b) {
    asm volatile("mma.sync.aligned.m16n8k16.row.col.f32.f16.f16.f32 "
                 "{%0,%1,%2,%3}, {%4,%5,%6,%7}, {%8,%9}, {%0,%1,%2,%3};"
                 : "+f"(c[0]), "+f"(c[1]), "+f"(c[2]), "+f"(c[3])
                 : "r"(a[0]), "r"(a[1]), "r"(a[2]), "r"(a[3]),
                   "r"(b[0]), "r"(b[1]));
}
__device__ __forceinline__ void cp_async16(u32 dst, const void* src) {
    asm volatile("cp.async.cg.shared.global [%0], [%1], 16;"
                 :: "r"(dst), "l"(src) : "memory");
}
#define CP_COMMIT() asm volatile("cp.async.commit_group;" ::: "memory")
#define CP_WAIT0()  asm volatile("cp.async.wait_group 0;" ::: "memory")

__device__ __forceinline__ float fast_sigmoid(float v) {
    return 1.0f / (1.0f + __expf(-v));
}

// ============================================================================
// K0: prep W' -> fp16 SW128-swizzled smem image per kchunk; also zeroes out[]
// (needed because the fused kernel accumulates into out with atomicAdd).
// ============================================================================
__global__ void __launch_bounds__(256) prep_kernel(const float* __restrict__ Wc,
                                                   float* __restrict__ out) {
    const int mo = blockIdx.x;
    const int c  = threadIdx.x;

    if (mo < (BB * SS * CC) / 256)            // 64 blocks zero out[16384]
        out[mo * 256 + c] = 0.0f;

    float w = 0.0f;
    if (mo < 216) {
        int s = mo & 7, tap = mo >> 3;
        w = Wc[((size_t)s * CC + c) * 27 + tap];
    }
    __half h = __float2half_rn(w);
    const int kc = c >> 6;
    const u32 kb = (u32)((c & 63) * 2) ^ (u32)((mo & 7) << 4);
    const size_t idx = (size_t)kc * (BROWS * 64) + ((u32)mo * 128 + kb) / 2;
    unsigned short hb;
    memcpy(&hb, &h, 2);
    ((unsigned short*)g_Bh4)[idx] = hb;
}

// ============================================================================
// K1: GEMM u[m][mo] = sum_k x[k][m] * W'[mo][k].   [R15: single XF buffer]
// grid = B*128, block 256 (8 warps = 4 m-groups x 2 n-halves).
// ============================================================================
__global__ void __launch_bounds__(256) gemm_kernel(const float* __restrict__ x) {
    extern __shared__ char smem[];
    const u32 sb = smem_u32(smem);
    const int tid = threadIdx.x, lane = tid & 31, warp = tid >> 5;
    const int mg = warp & 3, nh = warp >> 2;
    const int b  = blockIdx.x >> 7;
    const int n0 = (blockIdx.x & 127) * 128;

    float acc[7][2][2][4];
#pragma unroll
    for (int p = 0; p < 7; p++)
#pragma unroll
        for (int t = 0; t < 2; t++)
#pragma unroll
            for (int m = 0; m < 2; m++)
#pragma unroll
                for (int i = 0; i < 4; i++) acc[p][t][m][i] = 0.0f;

    const u32 xm     = (u32)(lane & 7) << 4;
    const int arow   = (lane & 7) + ((lane >> 3) & 1) * 8;
    const u32 a_ksel = (u32)((lane >> 4) & 1) * 16;
    const u32 b_ksel = (u32)((lane >> 3) & 1) * 16;
    const int btile  = (lane >> 4);
    const int brow   = lane & 7;

    const int mt0 = mg * 32;
    const u32 aXh0 = sb + XH_OFF + (u32)(mt0 + arow) * 128;
    const u32 aXh1 = aXh0 + 16 * 128;

    const float* xg = x + (size_t)b * CC * NN + n0;
    const int cm  = tid & 127;
    const int ckh = tid >> 7;
    const u32 cxm = (u32)(cm & 7) << 4;
    u32* xh_out = g_xh2 + (size_t)b * (CC / 2) * NN + n0 + cm;

    auto fill_x = [&](int kc) {
        const u32 dst = sb + XF_OFF;
#pragma unroll
        for (int p = 0; p < 8; p++) {
            int u = tid + p * 256;
            int row = u >> 5, col = u & 31;
            cp_async16(dst + (u32)row * 512 + (u32)col * 16,
                       xg + (size_t)(kc * 64 + row) * NN + col * 4);
        }
    };
    auto fill_B = [&](int kc) {
        const u32 dst = sb + (u32)((kc & 1) ? B1_OFF : B0_OFF);
        const char* src = ((const char*)g_Bh4) + (size_t)kc * B_IMG;
#pragma unroll
        for (int p = 0; p < 7; p++) {
            int u = tid + p * 256;
            cp_async16(dst + (u32)u * 16, src + (size_t)u * 16);
        }
    };

    fill_x(0); fill_B(0); CP_COMMIT();

#pragma unroll 1
    for (int kc = 0; kc < 4; kc++) {
        CP_WAIT0();
        __syncthreads();

        // ---- convert fp32 smem -> fp16 swizzled tile + g_xh2 dump ----
        {
            const float* xf = (const float*)(smem + XF_OFF);
            u32 hp[16];
#pragma unroll
            for (int u = 0; u < 16; u++) {
                float f0 = xf[(ckh * 32 + 2 * u) * 128 + cm];
                float f1 = xf[(ckh * 32 + 2 * u + 1) * 128 + cm];
                __half2 h2 = __floats2half2_rn(f0, f1);
                memcpy(&hp[u], &h2, 4);
            }
#pragma unroll
            for (int j = 0; j < 4; j++) {
                u32 off = ((u32)(ckh * 64 + j * 16)) ^ cxm;
                uint4 v4 = make_uint4(hp[4 * j], hp[4 * j + 1],
                                      hp[4 * j + 2], hp[4 * j + 3]);
                *(uint4*)(smem + XH_OFF + cm * 128 + off) = v4;
            }
            u32* xo = xh_out + (size_t)(kc * 32 + ckh * 16) * NN;
#pragma unroll
            for (int u = 0; u < 16; u++)
                xo[(size_t)u * NN] = hp[u];
        }
        __syncthreads();   // XF consumed by all; XH ready for all

        // ---- prefetch next chunk (x into freed XF, B into other buffer) ----
        if (kc < 3) { fill_x(kc + 1); fill_B(kc + 1); CP_COMMIT(); }

        // ---- compute: 4 k16 steps ----
        const u32 Bbase = sb + (u32)((kc & 1) ? B1_OFF : B0_OFF);
#pragma unroll
        for (int j = 0; j < 4; j++) {
            const u32 ka  = ((u32)(j * 32) + a_ksel) ^ xm;
            const u32 kb2 = ((u32)(j * 32) + b_ksel) ^ xm;
            u32 Ah0[4], Ah1[4];
            ldm4(Ah0, aXh0 + ka); ldm4(Ah1, aXh1 + ka);
#pragma unroll
            for (int p = 0; p < 7; p++) {
                const int tile = nh * 14 + 2 * p + btile;
                const u32 boff = (u32)(tile * 8 + brow) * 128 + kb2;
                u32 Bf[4];
                ldm4(Bf, Bbase + boff);
                mma16816(acc[p][0][0], Ah0, Bf);
                mma16816(acc[p][0][1], Ah1, Bf);
                mma16816(acc[p][1][0], Ah0, Bf + 2);
                mma16816(acc[p][1][1], Ah1, Bf + 2);
            }
        }
    }

    // ---- epilogue: fp16 u stores (tile == tap) ----
    const int mrow = lane >> 2;
    const int q    = lane & 3;
    u32* up = (u32*)g_u3;
#pragma unroll
    for (int p = 0; p < 7; p++)
#pragma unroll
        for (int tt = 0; tt < 2; tt++) {
            const int tile = nh * 14 + 2 * p + tt;
            if (tile >= NTAP) continue;
#pragma unroll
            for (int mi = 0; mi < 2; mi++) {
                const float* cf = acc[p][tt][mi];
                const int m = n0 + mt0 + mi * 16 + mrow;
                const size_t base = ((size_t)(b * NTAP + tile) * NN + m) * 4 + q;
                __half2 h01 = __floats2half2_rn(cf[0], cf[1]);
                __half2 h23 = __floats2half2_rn(cf[2], cf[3]);
                u32 w01, w23;
                memcpy(&w01, &h01, 4); memcpy(&w23, &h23, 4);
                up[base]      = w01;
                up[base + 32] = w23;
            }
        }
}

// ============================================================================
// K2: FUSED shift-add + sigmoid + einsum (tensor cores); epilogue accumulates
// straight into out[] with atomicAdd (out pre-zeroed by prep).
// grid = B*NK = 128 CTAs, 512 threads.
// ============================================================================
__global__ void __launch_bounds__(ETHREADS) einsum_fused_kernel(
    const float* __restrict__ bias, float* __restrict__ out)
{
    extern __shared__ __half esm[];
    __half* sx0  = esm;                    // 3 x E_SX_HALFS
    __half* ssel = esm + E_SEL_BASE;       // 16 x SELROW

    const int b = blockIdx.x >> 4;
    const int v = blockIdx.x & (NK - 1);
    const int tid = threadIdx.x, lane = tid & 31, warp = tid >> 5;
    const int kbase = v * (NN / NK);       // 1024 n per split

    // zero sel rows 8..15
    for (int i = tid; i < 8 * SELROW; i += ETHREADS)
        ssel[8 * SELROW + i] = __float2half(0.0f);

    // ---- Phase 1: shift-add + sigmoid for n in [kbase, kbase+1024) ----
    {
        const uint4* ub = (const uint4*)g_u3 + (size_t)b * NTAP * NN;
        float bs[SS];
#pragma unroll
        for (int s = 0; s < SS; s++) bs[s] = bias[s];

#pragma unroll
        for (int pass = 0; pass < 2; pass++) {
            const int nl = pass * ETHREADS + tid;
            const int n  = kbase + nl;
            const int d = n >> 10, h = (n >> 5) & 31, w = n & 31;

            float acc[SS];
#pragma unroll
            for (int s = 0; s < SS; s++) acc[s] = bs[s];

#pragma unroll
            for (int kd = 0; kd < 3; kd++) {
                const int dd = d + kd - 1;
                if ((unsigned)dd >= (unsigned)DD_) continue;
#pragma unroll
                for (int kh = 0; kh < 3; kh++) {
                    const int hh = h + kh - 1;
                    if ((unsigned)hh >= (unsigned)HH_) continue;
#pragma unroll
                    for (int kw = 0; kw < 3; kw++) {
                        const int ww = w + kw - 1;
                        if ((unsigned)ww >= (unsigned)WW_) continue;
                        const int tap = (kd * 3 + kh) * 3 + kw;
                        const int m = dd * PLANE + hh * WW_ + ww;
                        uint4 vv = ub[(size_t)tap * NN + m];
                        __half2 p0, p1, p2, p3;
                        memcpy(&p0, &vv.x, 4); memcpy(&p1, &vv.y, 4);
                        memcpy(&p2, &vv.z, 4); memcpy(&p3, &vv.w, 4);
                        float2 f0 = __half22float2(p0), f1 = __half22float2(p1);
                        float2 f2 = __half22float2(p2), f3 = __half22float2(p3);
                        acc[0] += f0.x; acc[1] += f0.y; acc[2] += f1.x; acc[3] += f1.y;
                        acc[4] += f2.x; acc[5] += f2.y; acc[6] += f3.x; acc[7] += f3.y;
                    }
                }
            }
#pragma unroll
            for (int s = 0; s < SS; s++)
                ssel[s * SELROW + nl] = __float2half_rn(fast_sigmoid(acc[s]));
        }
    }

    // ---- Phase 2: einsum over 16 windows of 64 n ----
    const u32* xsrc = g_xh2 + (size_t)b * (CC / 2) * NN + kbase;

    float acc0[4], acc1[4];
#pragma unroll
    for (int i = 0; i < 4; i++) { acc0[i] = 0.0f; acc1[i] = 0.0f; }

    const u32 sxb  = smem_u32(sx0);
    const u32 selb = smem_u32(ssel);
    const int a_row  = (lane & 7) + ((lane >> 3) & 1) * 8;
    const u32 a_kblk = (u32)((lane >> 4) & 1) * 8;      // halfs
    const int bt_loc = (lane >> 4);                     // B-addressing role only
    const u32 b_kblk = (u32)((lane >> 3) & 1) * 8;      // halfs
    const int b_row  = lane & 7;
    const int ct     = warp * 2 + bt_loc;
    const u32 bAddrC = (u32)(ct * 8 + b_row) * (XST * 2) + b_kblk * 2;
    const u32 aAddrC = selb + (u32)a_row * (SELROW * 2) + a_kblk * 2;

    const int row_ = tid >> 4, q_ = tid & 15;   // LOADX/STOREX lane mapping

#define LOADX(xr, w) do {                                                     \
    _Pragma("unroll")                                                         \
    for (int p = 0; p < 4; p++) {                                             \
        int r2 = row_ + p * 32;                                               \
        (xr)[p] = *(const uint4*)(xsrc + (size_t)r2 * NN + (w) * KW + q_ * 4);\
    }                                                                         \
} while (0)

#define STOREX(bufi, xr) do {                                                 \
    __half* sxw = sx0 + (bufi) * E_SX_HALFS;                                  \
    _Pragma("unroll")                                                         \
    for (int p = 0; p < 4; p++) {                                             \
        int r2 = row_ + p * 32;                                               \
        u32 e01 = __byte_perm((xr)[p].x, (xr)[p].y, 0x5410);                  \
        u32 e23 = __byte_perm((xr)[p].z, (xr)[p].w, 0x5410);                  \
        u32 o01 = __byte_perm((xr)[p].x, (xr)[p].y, 0x7632);                  \
        u32 o23 = __byte_perm((xr)[p].z, (xr)[p].w, 0x7632);                  \
        *(uint2*)&sxw[(2 * r2) * XST + q_ * 4]     = make_uint2(e01, e23);    \
        *(uint2*)&sxw[(2 * r2 + 1) * XST + q_ * 4] = make_uint2(o01, o23);    \
    }                                                                         \
} while (0)

#define COMPUTEX(bufi, w) do {                                                \
    const u32 sxbase = sxb + (u32)(bufi) * E_SX_HALFS * 2;                    \
    _Pragma("unroll")                                                         \
    for (int ks = 0; ks < KW / 16; ks++) {                                    \
        u32 A[4];                                                             \
        ldm4(A, aAddrC + ((u32)((w) * KW + ks * 16)) * 2);                    \
        u32 Bf[4];                                                            \
        ldm4(Bf, sxbase + bAddrC + (u32)(ks * 16) * 2);                       \
        mma16816(acc0, A, Bf);                                                \
        mma16816(acc1, A, Bf + 2);                                            \
    }                                                                         \
} while (0)

    uint4 xrA[4], xrB[4];
    LOADX(xrA, 0);
    LOADX(xrB, 1);

#pragma unroll 1
    for (int wp = 0; wp < 8; wp++) {
        const int w0 = 2 * wp, w1 = w0 + 1;
        STOREX(w0 % 3, xrA);
        __syncthreads();
        if (w0 + 2 < 16) LOADX(xrA, w0 + 2);
        COMPUTEX(w0 % 3, w0);
        __syncthreads();
        STOREX(w1 % 3, xrB);
        __syncthreads();
        if (w1 + 2 < 16) LOADX(xrB, w1 + 2);
        COMPUTEX(w1 % 3, w1);
        __syncthreads();
    }

    // epilogue: acc0 = tile warp*2, acc1 = tile warp*2+1 for ALL lanes.
    // Accumulate straight into out (pre-zeroed; pre-scaled by 1/N).
    const int s = lane >> 2;
    {
        const int c0 = warp * 16 + (lane & 3) * 2;
        float* dst = &out[(size_t)(b * SS + s) * CC + c0];
        const float inv = 1.0f / (float)NN;
        atomicAdd(dst + 0, acc0[0] * inv);
        atomicAdd(dst + 1, acc0[1] * inv);
        atomicAdd(dst + 8, acc1[0] * inv);
        atomicAdd(dst + 9, acc1[1] * inv);
    }
#undef LOADX
#undef STOREX
#undef COMPUTEX
}

// ============================================================================
extern "C" void kernel_launch(void* const* d_in, const int* in_sizes, int n_in,
                              void* d_out, int out_size) {
    const float* x    = (const float*)d_in[0];   // [8,256,16,32,32]
    const float* Wc   = (const float*)d_in[1];   // [8,256,3,3,3]
    const float* bias = (const float*)d_in[2];   // [8]
    float* out = (float*)d_out;                  // [8,8,256]

    cudaFuncSetAttribute(gemm_kernel,
                         cudaFuncAttributeMaxDynamicSharedMemorySize, GEMM_SMEM);
    cudaFuncSetAttribute(einsum_fused_kernel,
                         cudaFuncAttributeMaxDynamicSharedMemorySize, EINSUM_SMEM);

    prep_kernel<<<BROWS, 256>>>(Wc, out);
    gemm_kernel<<<BB * (NN / 128), 256, GEMM_SMEM>>>(x);
    einsum_fused_kernel<<<BB * NK, ETHREADS, EINSUM_SMEM>>>(bias, out);
}

// round 17
// speedup vs baseline: 1.1579x; 1.0058x over previous
#include <cuda_runtime.h>
#include <cuda_fp16.h>
#include <cstdint>
#include <cstring>

#define BB   8
#define CC   256
#define DD_  16
#define HH_  32
#define WW_  32
#define SS   8
#define NN   16384
#define PLANE 1024
#define NTAP 27
#define BROWS 224            // padded mo rows (28 tiles of 8)
#define B_IMG 28672          // bytes per kchunk W' image

// GEMM smem offsets (bytes) — single fp32 x buffer, 104KB total
#define XF_OFF  0            // fp32 x chunk: 64c x 128n x 4B = 32KB
#define XH_OFF  32768        // fp16 swizzled x tile: 128 rows x 128B = 16KB
#define B0_OFF  49152
#define B1_OFF  77824
#define GEMM_SMEM 106496

// fused shiftadd+einsum
#define NK 16
#define KW 64
#define XST 72               // halfs per x row (144B, conflict-free ldmatrix)
#define SELROW 1032          // halfs per sel row (2064B; same bank class as 144)
#define E_SX_HALFS  (256 * XST)            // per x buffer (36,864B)
#define E_SEL_BASE  (3 * E_SX_HALFS)       // half-index where sel starts
#define E_SEL_HALFS (16 * SELROW)
#define EINSUM_SMEM ((3 * E_SX_HALFS + E_SEL_HALFS) * 2)   // 143,616 bytes
#define ETHREADS 512

typedef unsigned int u32;
typedef unsigned long long ull;

// ---------------- scratch ----------------
__device__ __half g_u3[(size_t)BB * NTAP * NN * SS];   // [b][tap][m][s]
__device__ u32    g_xh2[(size_t)BB * (CC / 2) * NN];   // [b][cpair][n] fp16 pairs
__device__ int4   g_Bh4[4 * BROWS * 8];                // 4 kchunks x 224 rows x 128B

// ---------------- helpers ----------------
__device__ __forceinline__ u32 smem_u32(const void* p) {
    u32 a;
    asm("{ .reg .u64 t; cvta.to.shared.u64 t, %1; cvt.u32.u64 %0, t; }"
        : "=r"(a) : "l"(p));
    return a;
}
__device__ __forceinline__ void ldm4(u32* r, u32 addr) {
    asm volatile("ldmatrix.sync.aligned.m8n8.x4.shared.b16 {%0,%1,%2,%3}, [%4];"
                 : "=r"(r[0]), "=r"(r[1]), "=r"(r[2]), "=r"(r[3]) : "r"(addr));
}
__device__ __forceinline__ void mma16816(float* c, const u32* a, const u32* b) {
    asm volatile("mma.sync.aligned.m16n8k16.row.col.f32.f16.f16.f32 "
                 "{%0,%1,%2,%3}, {%4,%5,%6,%7}, {%8,%9}, {%0,%1,%2,%3};"
                 : "+f"(c[0]), "+f"(c[1]), "+f"(c[2]), "+f"(c[3])
                 : "r"(a[0]), "r"(a[1]), "r"(a[2]), "r"(a[3]),
                   "r"(b[0]), "r"(b[1]));
}
__device__ __forceinline__ void cp_async16(u32 dst, const void* src) {
    asm volatile("cp.async.cg.shared.global [%0], [%1], 16;"
                 :: "r"(dst), "l"(src) : "memory");
}
#define CP_COMMIT() asm volatile("cp.async.commit_group;" ::: "memory")
#define CP_WAIT0()  asm volatile("cp.async.wait_group 0;" ::: "memory")

__device__ __forceinline__ float fast_sigmoid(float v) {
    return 1.0f / (1.0f + __expf(-v));
}

// ============================================================================
// K0: prep W' -> fp16 SW128-swizzled smem image per kchunk; also zeroes out[].
// ============================================================================
__global__ void __launch_bounds__(256) prep_kernel(const float* __restrict__ Wc,
                                                   float* __restrict__ out) {
    const int mo = blockIdx.x;
    const int c  = threadIdx.x;

    if (mo < (BB * SS * CC) / 256)            // 64 blocks zero out[16384]
        out[mo * 256 + c] = 0.0f;

    float w = 0.0f;
    if (mo < 216) {
        int s = mo & 7, tap = mo >> 3;
        w = Wc[((size_t)s * CC + c) * 27 + tap];
    }
    __half h = __float2half_rn(w);
    const int kc = c >> 6;
    const u32 kb = (u32)((c & 63) * 2) ^ (u32)((mo & 7) << 4);
    const size_t idx = (size_t)kc * (BROWS * 64) + ((u32)mo * 128 + kb) / 2;
    unsigned short hb;
    memcpy(&hb, &h, 2);
    ((unsigned short*)g_Bh4)[idx] = hb;
}

// ============================================================================
// K1: GEMM u[m][mo] = sum_k x[k][m] * W'[mo][k].   [R15/R16 best]
// grid = B*128, block 256 (8 warps = 4 m-groups x 2 n-halves).
// ============================================================================
__global__ void __launch_bounds__(256) gemm_kernel(const float* __restrict__ x) {
    extern __shared__ char smem[];
    const u32 sb = smem_u32(smem);
    const int tid = threadIdx.x, lane = tid & 31, warp = tid >> 5;
    const int mg = warp & 3, nh = warp >> 2;
    const int b  = blockIdx.x >> 7;
    const int n0 = (blockIdx.x & 127) * 128;

    float acc[7][2][2][4];
#pragma unroll
    for (int p = 0; p < 7; p++)
#pragma unroll
        for (int t = 0; t < 2; t++)
#pragma unroll
            for (int m = 0; m < 2; m++)
#pragma unroll
                for (int i = 0; i < 4; i++) acc[p][t][m][i] = 0.0f;

    const u32 xm     = (u32)(lane & 7) << 4;
    const int arow   = (lane & 7) + ((lane >> 3) & 1) * 8;
    const u32 a_ksel = (u32)((lane >> 4) & 1) * 16;
    const u32 b_ksel = (u32)((lane >> 3) & 1) * 16;
    const int btile  = (lane >> 4);
    const int brow   = lane & 7;

    const int mt0 = mg * 32;
    const u32 aXh0 = sb + XH_OFF + (u32)(mt0 + arow) * 128;
    const u32 aXh1 = aXh0 + 16 * 128;

    const float* xg = x + (size_t)b * CC * NN + n0;
    const int cm  = tid & 127;
    const int ckh = tid >> 7;
    const u32 cxm = (u32)(cm & 7) << 4;
    u32* xh_out = g_xh2 + (size_t)b * (CC / 2) * NN + n0 + cm;

    auto fill_x = [&](int kc) {
        const u32 dst = sb + XF_OFF;
#pragma unroll
        for (int p = 0; p < 8; p++) {
            int u = tid + p * 256;
            int row = u >> 5, col = u & 31;
            cp_async16(dst + (u32)row * 512 + (u32)col * 16,
                       xg + (size_t)(kc * 64 + row) * NN + col * 4);
        }
    };
    auto fill_B = [&](int kc) {
        const u32 dst = sb + (u32)((kc & 1) ? B1_OFF : B0_OFF);
        const char* src = ((const char*)g_Bh4) + (size_t)kc * B_IMG;
#pragma unroll
        for (int p = 0; p < 7; p++) {
            int u = tid + p * 256;
            cp_async16(dst + (u32)u * 16, src + (size_t)u * 16);
        }
    };

    fill_x(0); fill_B(0); CP_COMMIT();

#pragma unroll 1
    for (int kc = 0; kc < 4; kc++) {
        CP_WAIT0();
        __syncthreads();

        // ---- convert fp32 smem -> fp16 swizzled tile + g_xh2 dump ----
        {
            const float* xf = (const float*)(smem + XF_OFF);
            u32 hp[16];
#pragma unroll
            for (int u = 0; u < 16; u++) {
                float f0 = xf[(ckh * 32 + 2 * u) * 128 + cm];
                float f1 = xf[(ckh * 32 + 2 * u + 1) * 128 + cm];
                __half2 h2 = __floats2half2_rn(f0, f1);
                memcpy(&hp[u], &h2, 4);
            }
#pragma unroll
            for (int j = 0; j < 4; j++) {
                u32 off = ((u32)(ckh * 64 + j * 16)) ^ cxm;
                uint4 v4 = make_uint4(hp[4 * j], hp[4 * j + 1],
                                      hp[4 * j + 2], hp[4 * j + 3]);
                *(uint4*)(smem + XH_OFF + cm * 128 + off) = v4;
            }
            u32* xo = xh_out + (size_t)(kc * 32 + ckh * 16) * NN;
#pragma unroll
            for (int u = 0; u < 16; u++)
                xo[(size_t)u * NN] = hp[u];
        }
        __syncthreads();   // XF consumed by all; XH ready for all

        // ---- prefetch next chunk (x into freed XF, B into other buffer) ----
        if (kc < 3) { fill_x(kc + 1); fill_B(kc + 1); CP_COMMIT(); }

        // ---- compute: 4 k16 steps ----
        const u32 Bbase = sb + (u32)((kc & 1) ? B1_OFF : B0_OFF);
#pragma unroll
        for (int j = 0; j < 4; j++) {
            const u32 ka  = ((u32)(j * 32) + a_ksel) ^ xm;
            const u32 kb2 = ((u32)(j * 32) + b_ksel) ^ xm;
            u32 Ah0[4], Ah1[4];
            ldm4(Ah0, aXh0 + ka); ldm4(Ah1, aXh1 + ka);
#pragma unroll
            for (int p = 0; p < 7; p++) {
                const int tile = nh * 14 + 2 * p + btile;
                const u32 boff = (u32)(tile * 8 + brow) * 128 + kb2;
                u32 Bf[4];
                ldm4(Bf, Bbase + boff);
                mma16816(acc[p][0][0], Ah0, Bf);
                mma16816(acc[p][0][1], Ah1, Bf);
                mma16816(acc[p][1][0], Ah0, Bf + 2);
                mma16816(acc[p][1][1], Ah1, Bf + 2);
            }
        }
    }

    // ---- epilogue: fp16 u stores (tile == tap) ----
    const int mrow = lane >> 2;
    const int q    = lane & 3;
    u32* up = (u32*)g_u3;
#pragma unroll
    for (int p = 0; p < 7; p++)
#pragma unroll
        for (int tt = 0; tt < 2; tt++) {
            const int tile = nh * 14 + 2 * p + tt;
            if (tile >= NTAP) continue;
#pragma unroll
            for (int mi = 0; mi < 2; mi++) {
                const float* cf = acc[p][tt][mi];
                const int m = n0 + mt0 + mi * 16 + mrow;
                const size_t base = ((size_t)(b * NTAP + tile) * NN + m) * 4 + q;
                __half2 h01 = __floats2half2_rn(cf[0], cf[1]);
                __half2 h23 = __floats2half2_rn(cf[2], cf[3]);
                u32 w01, w23;
                memcpy(&w01, &h01, 4); memcpy(&w23, &h23, 4);
                up[base]      = w01;
                up[base + 32] = w23;
            }
        }
}

// ============================================================================
// K2: FUSED shift-add + sigmoid + einsum; atomicAdd epilogue into out.
// grid = B*NK = 128 CTAs, 512 threads.
// Phase 2 now uses ONE sync per window (3-buffer rotation makes the second
// barrier redundant: store buffer is always disjoint from any in-flight
// compute buffer, and overwrites a buffer computed >= 2 syncs ago).
// ============================================================================
__global__ void __launch_bounds__(ETHREADS) einsum_fused_kernel(
    const float* __restrict__ bias, float* __restrict__ out)
{
    extern __shared__ __half esm[];
    __half* sx0  = esm;                    // 3 x E_SX_HALFS
    __half* ssel = esm + E_SEL_BASE;       // 16 x SELROW

    const int b = blockIdx.x >> 4;
    const int v = blockIdx.x & (NK - 1);
    const int tid = threadIdx.x, lane = tid & 31, warp = tid >> 5;
    const int kbase = v * (NN / NK);       // 1024 n per split

    // zero sel rows 8..15
    for (int i = tid; i < 8 * SELROW; i += ETHREADS)
        ssel[8 * SELROW + i] = __float2half(0.0f);

    // ---- Phase 1: shift-add + sigmoid for n in [kbase, kbase+1024) ----
    {
        const uint4* ub = (const uint4*)g_u3 + (size_t)b * NTAP * NN;
        float bs[SS];
#pragma unroll
        for (int s = 0; s < SS; s++) bs[s] = bias[s];

#pragma unroll
        for (int pass = 0; pass < 2; pass++) {
            const int nl = pass * ETHREADS + tid;
            const int n  = kbase + nl;
            const int d = n >> 10, h = (n >> 5) & 31, w = n & 31;

            float acc[SS];
#pragma unroll
            for (int s = 0; s < SS; s++) acc[s] = bs[s];

#pragma unroll
            for (int kd = 0; kd < 3; kd++) {
                const int dd = d + kd - 1;
                if ((unsigned)dd >= (unsigned)DD_) continue;
#pragma unroll
                for (int kh = 0; kh < 3; kh++) {
                    const int hh = h + kh - 1;
                    if ((unsigned)hh >= (unsigned)HH_) continue;
#pragma unroll
                    for (int kw = 0; kw < 3; kw++) {
                        const int ww = w + kw - 1;
                        if ((unsigned)ww >= (unsigned)WW_) continue;
                        const int tap = (kd * 3 + kh) * 3 + kw;
                        const int m = dd * PLANE + hh * WW_ + ww;
                        uint4 vv = ub[(size_t)tap * NN + m];
                        __half2 p0, p1, p2, p3;
                        memcpy(&p0, &vv.x, 4); memcpy(&p1, &vv.y, 4);
                        memcpy(&p2, &vv.z, 4); memcpy(&p3, &vv.w, 4);
                        float2 f0 = __half22float2(p0), f1 = __half22float2(p1);
                        float2 f2 = __half22float2(p2), f3 = __half22float2(p3);
                        acc[0] += f0.x; acc[1] += f0.y; acc[2] += f1.x; acc[3] += f1.y;
                        acc[4] += f2.x; acc[5] += f2.y; acc[6] += f3.x; acc[7] += f3.y;
                    }
                }
            }
#pragma unroll
            for (int s = 0; s < SS; s++)
                ssel[s * SELROW + nl] = __float2half_rn(fast_sigmoid(acc[s]));
        }
    }

    // ---- Phase 2: einsum over 16 windows of 64 n (one sync per window) ----
    const u32* xsrc = g_xh2 + (size_t)b * (CC / 2) * NN + kbase;

    float acc0[4], acc1[4];
#pragma unroll
    for (int i = 0; i < 4; i++) { acc0[i] = 0.0f; acc1[i] = 0.0f; }

    const u32 sxb  = smem_u32(sx0);
    const u32 selb = smem_u32(ssel);
    const int a_row  = (lane & 7) + ((lane >> 3) & 1) * 8;
    const u32 a_kblk = (u32)((lane >> 4) & 1) * 8;      // halfs
    const int bt_loc = (lane >> 4);                     // B-addressing role only
    const u32 b_kblk = (u32)((lane >> 3) & 1) * 8;      // halfs
    const int b_row  = lane & 7;
    const int ct     = warp * 2 + bt_loc;
    const u32 bAddrC = (u32)(ct * 8 + b_row) * (XST * 2) + b_kblk * 2;
    const u32 aAddrC = selb + (u32)a_row * (SELROW * 2) + a_kblk * 2;

    const int row_ = tid >> 4, q_ = tid & 15;   // LOADX/STOREX lane mapping

#define LOADX(xr, w) do {                                                     \
    _Pragma("unroll")                                                         \
    for (int p = 0; p < 4; p++) {                                             \
        int r2 = row_ + p * 32;                                               \
        (xr)[p] = *(const uint4*)(xsrc + (size_t)r2 * NN + (w) * KW + q_ * 4);\
    }                                                                         \
} while (0)

#define STOREX(bufi, xr) do {                                                 \
    __half* sxw = sx0 + (bufi) * E_SX_HALFS;                                  \
    _Pragma("unroll")                                                         \
    for (int p = 0; p < 4; p++) {                                             \
        int r2 = row_ + p * 32;                                               \
        u32 e01 = __byte_perm((xr)[p].x, (xr)[p].y, 0x5410);                  \
        u32 e23 = __byte_perm((xr)[p].z, (xr)[p].w, 0x5410);                  \
        u32 o01 = __byte_perm((xr)[p].x, (xr)[p].y, 0x7632);                  \
        u32 o23 = __byte_perm((xr)[p].z, (xr)[p].w, 0x7632);                  \
        *(uint2*)&sxw[(2 * r2) * XST + q_ * 4]     = make_uint2(e01, e23);    \
        *(uint2*)&sxw[(2 * r2 + 1) * XST + q_ * 4] = make_uint2(o01, o23);    \
    }                                                                         \
} while (0)

#define COMPUTEX(bufi, w) do {                                                \
    const u32 sxbase = sxb + (u32)(bufi) * E_SX_HALFS * 2;                    \
    _Pragma("unroll")                                                         \
    for (int ks = 0; ks < KW / 16; ks++) {                                    \
        u32 A[4];                                                             \
        ldm4(A, aAddrC + ((u32)((w) * KW + ks * 16)) * 2);                    \
        u32 Bf[4];                                                            \
        ldm4(Bf, sxbase + bAddrC + (u32)(ks * 16) * 2);                       \
        mma16816(acc0, A, Bf);                                                \
        mma16816(acc1, A, Bf + 2);                                            \
    }                                                                         \
} while (0)

    uint4 xrA[4], xrB[4];
    LOADX(xrA, 0);
    LOADX(xrB, 1);

#pragma unroll 1
    for (int wp = 0; wp < 8; wp++) {
        const int w0 = 2 * wp, w1 = w0 + 1;
        STOREX(w0 % 3, xrA);
        __syncthreads();
        if (w0 + 2 < 16) LOADX(xrA, w0 + 2);
        COMPUTEX(w0 % 3, w0);
        STOREX(w1 % 3, xrB);          // distinct buffer from w0's compute
        __syncthreads();
        if (w1 + 2 < 16) LOADX(xrB, w1 + 2);
        COMPUTEX(w1 % 3, w1);
    }

    // epilogue: acc0 = tile warp*2, acc1 = tile warp*2+1 for ALL lanes.
    const int s = lane >> 2;
    {
        const int c0 = warp * 16 + (lane & 3) * 2;
        float* dst = &out[(size_t)(b * SS + s) * CC + c0];
        const float inv = 1.0f / (float)NN;
        atomicAdd(dst + 0, acc0[0] * inv);
        atomicAdd(dst + 1, acc0[1] * inv);
        atomicAdd(dst + 8, acc1[0] * inv);
        atomicAdd(dst + 9, acc1[1] * inv);
    }
#undef LOADX
#undef STOREX
#undef COMPUTEX
}

// ============================================================================
extern "C" void kernel_launch(void* const* d_in, const int* in_sizes, int n_in,
                              void* d_out, int out_size) {
    const float* x    = (const float*)d_in[0];   // [8,256,16,32,32]
    const float* Wc   = (const float*)d_in[1];   // [8,256,3,3,3]
    const float* bias = (const float*)d_in[2];   // [8]
    float* out = (float*)d_out;                  // [8,8,256]

    cudaFuncSetAttribute(gemm_kernel,
                         cudaFuncAttributeMaxDynamicSharedMemorySize, GEMM_SMEM);
    cudaFuncSetAttribute(einsum_fused_kernel,
                         cudaFuncAttributeMaxDynamicSharedMemorySize, EINSUM_SMEM);

    prep_kernel<<<BROWS, 256>>>(Wc, out);
    gemm_kernel<<<BB * (NN / 128), 256, GEMM_SMEM>>>(x);
    einsum_fused_kernel<<<BB * NK, ETHREADS, EINSUM_SMEM>>>(bias, out);
}